// round 3
// baseline (speedup 1.0000x reference)
#include <cuda_runtime.h>
#include <cstdint>

// GramsEmbedding: out[b,s,:] = sum over UNIQUE v in {idx[0,b,s], idx[1,b,s]} of weight[v,:]
// K=2, B=2, S=1024, V=32000, D=128.
//
// One thread per output element (262144 threads). Lean version:
//  - 512-thread CTAs -> 512 CTAs (halves CTA dispatch in the launch ramp)
//  - pure 32-bit address arithmetic (max byte offset 16 MB, fits easily)
//  - both gathers issued unconditionally (MLP=2 after the idx level),
//    duplicate zeroed branchlessly.

#define ROWS      2048      // B * S
#define D         128
#define THREADS   512

__global__ __launch_bounds__(THREADS, 4)
void grams_embedding_kernel(const int* __restrict__ idx,
                            const float* __restrict__ w,     // [32000][128]
                            float* __restrict__ out)         // [2048][128]
{
    int t    = blockIdx.x * THREADS + threadIdx.x;   // 0 .. 262143
    int row  = t >> 7;                                // 0 .. 2047
    int col  = t & 127;                               // 0 .. 127

    // Level 1: two independent idx loads (warp-broadcast, 1 sector each)
    int i0 = __ldg(&idx[row]);
    int i1 = __ldg(&idx[row + ROWS]);

    // Level 2: two independent gathers (coalesced 128B per warp), 32-bit offsets
    float a = __ldg(&w[i0 * D + col]);
    float b = __ldg(&w[i1 * D + col]);

    out[t] = a + (i1 != i0 ? b : 0.0f);
}

extern "C" void kernel_launch(void* const* d_in, const int* in_sizes, int n_in,
                              void* d_out, int out_size)
{
    const int*   idx = (const int*)d_in[0];
    const float* w   = (const float*)d_in[1];
    float*       out = (float*)d_out;

    grams_embedding_kernel<<<(ROWS * D) / THREADS, THREADS>>>(idx, w, out);
}

// round 4
// speedup vs baseline: 1.1840x; 1.1840x over previous
#include <cuda_runtime.h>
#include <cstdint>

// GramsEmbedding: out[b,s,:] = sum over UNIQUE v in {idx[0,b,s], idx[1,b,s]} of weight[v,:]
// K=2, B=2, S=1024, V=32000, D=128.
//
// ILP-2 version: each thread handles the SAME column of TWO rows (r and
// r+1024, i.e. batch 0 and batch 1 at the same seq position). That gives
// 4 independent idx loads then 4 independent weight gathers per thread
// (MLP=4 at each memory level), hiding DRAM latency with fewer threads.
// 131072 threads, 256 CTAs x 512. All accesses coalesced (idx broadcasts,
// gathers/stores are 128B per warp).

#define HALF_ROWS 1024      // rows handled per "plane"; pair = (r, r+1024)
#define ROWS      2048      // B * S
#define D         128
#define THREADS   512

__global__ __launch_bounds__(THREADS, 4)
void grams_embedding_kernel(const int* __restrict__ idx,
                            const float* __restrict__ w,     // [32000][128]
                            float* __restrict__ out)         // [2048][128]
{
    int t   = blockIdx.x * THREADS + threadIdx.x;    // 0 .. 131071
    int r   = t >> 7;                                 // 0 .. 1023
    int col = t & 127;                                // 0 .. 127

    // Level 1: 4 independent idx loads (each a warp-broadcast, 1 sector)
    int i0a = __ldg(&idx[r]);                         // gram0, batch0-row
    int i0b = __ldg(&idx[r + HALF_ROWS]);             // gram0, batch1-row
    int i1a = __ldg(&idx[r + ROWS]);                  // gram1, batch0-row
    int i1b = __ldg(&idx[r + ROWS + HALF_ROWS]);      // gram1, batch1-row

    // Level 2: 4 independent gathers (coalesced 128B per warp), 32-bit offsets
    float a0 = __ldg(&w[i0a * D + col]);
    float b0 = __ldg(&w[i0b * D + col]);
    float a1 = __ldg(&w[i1a * D + col]);
    float b1 = __ldg(&w[i1b * D + col]);

    out[ r              * D + col] = a0 + (i1a != i0a ? a1 : 0.0f);
    out[(r + HALF_ROWS) * D + col] = b0 + (i1b != i0b ? b1 : 0.0f);
}

extern "C" void kernel_launch(void* const* d_in, const int* in_sizes, int n_in,
                              void* d_out, int out_size)
{
    const int*   idx = (const int*)d_in[0];
    const float* w   = (const float*)d_in[1];
    float*       out = (float*)d_out;

    grams_embedding_kernel<<<(HALF_ROWS * D) / THREADS, THREADS>>>(idx, w, out);
}